// round 9
// baseline (speedup 1.0000x reference)
#include <cuda_runtime.h>
#include <cuda_bf16.h>
#include <math.h>
#include <stdint.h>

#define BATCH 2
#define SEQ   4096
#define DM    1024
#define DIP   4256
#define DI    2048
#define CDIM  2176
#define NH    32
#define HD    64
#define NSTATE 64
#define M_ROWS (BATCH*SEQ)   /* 8192 */

// ---------------- scratch (device globals; no allocations allowed) ----------------
__device__ float g_zx[(size_t)M_ROWS * DIP];
__device__ float g_conv[(size_t)M_ROWS * CDIM];
__device__ float g_dt[(size_t)M_ROWS * NH];
__device__ float g_dA[(size_t)M_ROWS * NH];
__device__ float g_y[(size_t)M_ROWS * DI];
__device__ float g_y2[(size_t)M_ROWS * DI];
__device__ float g_h[(size_t)M_ROWS * DM];
__device__ __nv_bfloat16 g_xhi[(size_t)M_ROWS * DM];
__device__ __nv_bfloat16 g_xlo[(size_t)M_ROWS * DM];
__device__ __nv_bfloat16 g_yhi[(size_t)M_ROWS * DI];
__device__ __nv_bfloat16 g_ylo[(size_t)M_ROWS * DI];
__device__ __nv_bfloat16 g_whi[(size_t)DIP * DM];
__device__ __nv_bfloat16 g_wlo[(size_t)DIP * DM];

// ---------------- baseline-ISA PTX helpers ----------------
__device__ __forceinline__ uint32_t smem_u32_of(const void* p) {
    uint32_t a;
    asm("{ .reg .u64 t; cvta.to.shared.u64 t, %1; cvt.u32.u64 %0, t; }" : "=r"(a) : "l"(p));
    return a;
}
__device__ __forceinline__ void cp16(uint32_t dst, const void* src) {
    asm volatile("cp.async.cg.shared.global [%0], [%1], 16;" :: "r"(dst), "l"(src));
}
__device__ __forceinline__ void cp_commit() {
    asm volatile("cp.async.commit_group;" ::: "memory");
}
template<int N> __device__ __forceinline__ void cp_wait() {
    asm volatile("cp.async.wait_group %0;" :: "n"(N) : "memory");
}
__device__ __forceinline__ void ldsm_x4(uint32_t* r, uint32_t addr) {
    asm volatile("ldmatrix.sync.aligned.m8n8.x4.shared.b16 {%0,%1,%2,%3}, [%4];"
                 : "=r"(r[0]), "=r"(r[1]), "=r"(r[2]), "=r"(r[3]) : "r"(addr));
}
__device__ __forceinline__ void mma16816(float* d, const uint32_t* a, uint32_t b0, uint32_t b1) {
    asm volatile("mma.sync.aligned.m16n8k16.row.col.f32.bf16.bf16.f32 "
                 "{%0,%1,%2,%3}, {%4,%5,%6,%7}, {%8,%9}, {%0,%1,%2,%3};"
                 : "+f"(d[0]), "+f"(d[1]), "+f"(d[2]), "+f"(d[3])
                 : "r"(a[0]), "r"(a[1]), "r"(a[2]), "r"(a[3]), "r"(b0), "r"(b1));
}
__device__ __forceinline__ void split_bf(float v, __nv_bfloat16& h, __nv_bfloat16& l) {
    h = __float2bfloat16(v);
    l = __float2bfloat16(v - __bfloat162float(h));
}

// ---------------- weight fp32 -> (hi, lo) bf16 ----------------
__global__ void cvt_hilo(const float* __restrict__ s, __nv_bfloat16* __restrict__ hi,
                         __nv_bfloat16* __restrict__ lo)
{
    const size_t idx = (size_t)blockIdx.x * blockDim.x + threadIdx.x;
    const float4 v = ((const float4*)s)[idx];
    __nv_bfloat16 h0,h1,h2,h3,l0,l1,l2,l3;
    split_bf(v.x,h0,l0); split_bf(v.y,h1,l1); split_bf(v.z,h2,l2); split_bf(v.w,h3,l3);
    __nv_bfloat162 a,b;
    a.x=h0; a.y=h1; b.x=h2; b.y=h3;
    ((__nv_bfloat162*)hi)[idx*2]=a; ((__nv_bfloat162*)hi)[idx*2+1]=b;
    a.x=l0; a.y=l1; b.x=l2; b.y=l3;
    ((__nv_bfloat162*)lo)[idx*2]=a; ((__nv_bfloat162*)lo)[idx*2+1]=b;
}

// ---------------- HMMA bf16-split GEMM v3 ----------------
// CTA tile 256x128, 8 warps (4x2), warp tile 64x64, BK=32.
// 3-stage cp.async pipeline, ONE __syncthreads per chunk; load(c+2) overlaps MMA(c).
// Inner MMAs ordered term-outermost: accumulator reuse distance = 8 independent MMAs.
#define ROWB   80
#define OFF_AH 0
#define OFF_AL (256 * ROWB)               /* 20480 */
#define OFF_BH (2 * 256 * ROWB)           /* 40960 */
#define OFF_BL (OFF_BH + 128 * ROWB)      /* 51200 */
#define STAGE  (OFF_BL + 128 * ROWB)      /* 61440 */
#define NSTAGE 3
#define GEMM_SMEM (NSTAGE * STAGE)        /* 184320 */

__global__ __launch_bounds__(256, 1)
void gemm_mma(const __nv_bfloat16* __restrict__ Ahi, const __nv_bfloat16* __restrict__ Alo,
              const __nv_bfloat16* __restrict__ Whi, const __nv_bfloat16* __restrict__ Wlo,
              const float* __restrict__ Res, float* __restrict__ C,
              int Nn, int K)
{
    extern __shared__ char smem[];
    const uint32_t sb = smem_u32_of(smem);
    const int tid  = threadIdx.x;
    const int wid  = tid >> 5;
    const int lane = tid & 31;
    const int bm = blockIdx.y * 256;
    const int bn = blockIdx.x * 128;
    const int wm = wid >> 1;
    const int wn = wid & 1;
    const int NC = K >> 5;

    float acc[4][8][4];
#pragma unroll
    for (int i = 0; i < 4; i++)
#pragma unroll
        for (int j = 0; j < 8; j++)
#pragma unroll
            for (int q = 0; q < 4; q++) acc[i][j][q] = 0.f;

    const int ra = tid;
    const int rb = tid >> 1;
    const int lc = (tid & 1) * 2;
    int brow = bn + rb; if (brow >= Nn) brow = Nn - 1;
    const __nv_bfloat16* pah = Ahi + (size_t)(bm + ra) * K;
    const __nv_bfloat16* pal = Alo + (size_t)(bm + ra) * K;
    const __nv_bfloat16* pbh = Whi + (size_t)brow * K;
    const __nv_bfloat16* pbl = Wlo + (size_t)brow * K;

#define LOAD_CHUNK(c) do {                                            \
    const uint32_t s0 = sb + ((c) % NSTAGE) * STAGE;                  \
    const int kof = (c) * 32;                                         \
    const uint32_t sa = s0 + ra * ROWB;                               \
    _Pragma("unroll")                                                 \
    for (int q = 0; q < 4; q++) {                                     \
        cp16(sa + OFF_AH + q * 16, pah + kof + q * 8);                \
        cp16(sa + OFF_AL + q * 16, pal + kof + q * 8);                \
    }                                                                 \
    const uint32_t sbr = s0 + rb * ROWB;                              \
    _Pragma("unroll")                                                 \
    for (int q = 0; q < 2; q++) {                                     \
        const int ch = lc + q;                                        \
        cp16(sbr + OFF_BH + ch * 16, pbh + kof + ch * 8);             \
        cp16(sbr + OFF_BL + ch * 16, pbl + kof + ch * 8);             \
    }                                                                 \
    cp_commit();                                                      \
} while (0)

    LOAD_CHUNK(0);
    if (NC > 1) LOAD_CHUNK(1);

    const int a_rb  = wm * 64 + (lane & 15);
    const int a_chk = (lane >> 4) * 16;
    const int b_rb  = wn * 64 + ((lane >> 4) << 3) + (lane & 7);
    const int b_chk = ((lane >> 3) & 1) * 16;

    for (int c = 0; c < NC; c++) {
        if (c + 1 < NC) cp_wait<1>(); else cp_wait<0>();
        __syncthreads();
        // stage (c+2)%NSTAGE was last read in iteration c-1; the barrier above
        // guarantees every warp finished those reads -> safe to overwrite now.
        if (c + 2 < NC) LOAD_CHUNK(c + 2);

        const uint32_t sbuf = sb + (c % NSTAGE) * STAGE;

#pragma unroll
        for (int ks = 0; ks < 2; ks++) {
            uint32_t ah[4][4], al[4][4];
#pragma unroll
            for (int im = 0; im < 4; im++) {
                const uint32_t addr = sbuf + (a_rb + im * 16) * ROWB + ks * 32 + a_chk;
                ldsm_x4(ah[im], addr + OFF_AH);
                ldsm_x4(al[im], addr + OFF_AL);
            }
#pragma unroll
            for (int g = 0; g < 4; g++) {
                uint32_t bh[4], bl[4];
                const uint32_t addr = sbuf + (b_rb + g * 16) * ROWB + ks * 32 + b_chk;
                ldsm_x4(bh, addr + OFF_BH);
                ldsm_x4(bl, addr + OFF_BL);
                // term 1: Ah*Bh — 8 independent accumulators
#pragma unroll
                for (int im = 0; im < 4; im++)
#pragma unroll
                    for (int hf = 0; hf < 2; hf++)
                        mma16816(acc[im][g*2+hf], ah[im], bh[hf*2], bh[hf*2+1]);
                // term 2: Ah*Bl
#pragma unroll
                for (int im = 0; im < 4; im++)
#pragma unroll
                    for (int hf = 0; hf < 2; hf++)
                        mma16816(acc[im][g*2+hf], ah[im], bl[hf*2], bl[hf*2+1]);
                // term 3: Al*Bh
#pragma unroll
                for (int im = 0; im < 4; im++)
#pragma unroll
                    for (int hf = 0; hf < 2; hf++)
                        mma16816(acc[im][g*2+hf], al[im], bh[hf*2], bh[hf*2+1]);
            }
        }
    }
#undef LOAD_CHUNK

    // epilogue
#pragma unroll
    for (int im = 0; im < 4; im++) {
        const int r0 = bm + wm * 64 + im * 16 + (lane >> 2);
#pragma unroll
        for (int j = 0; j < 8; j++) {
            const int n0 = bn + wn * 64 + j * 8;
            if (n0 < Nn) {
                const int cc = n0 + (lane & 3) * 2;
                float2 v0 = make_float2(acc[im][j][0], acc[im][j][1]);
                float2 v1 = make_float2(acc[im][j][2], acc[im][j][3]);
                if (Res) {
                    const float2 r0v = *(const float2*)&Res[(size_t)r0 * Nn + cc];
                    const float2 r1v = *(const float2*)&Res[(size_t)(r0 + 8) * Nn + cc];
                    v0.x += r0v.x; v0.y += r0v.y;
                    v1.x += r1v.x; v1.y += r1v.y;
                }
                *(float2*)&C[(size_t)r0 * Nn + cc] = v0;
                *(float2*)&C[(size_t)(r0 + 8) * Nn + cc] = v1;
            }
        }
    }
}

// ---------------- LayerNorm -> bf16 hi/lo ----------------
__global__ void ln_kernel(const float* __restrict__ x, const float* __restrict__ w,
                          const float* __restrict__ b,
                          __nv_bfloat16* __restrict__ ohi, __nv_bfloat16* __restrict__ olo)
{
    __shared__ float sh1[8], sh2[8];
    const int row = blockIdx.x;
    const int tid = threadIdx.x;
    const float4 v = ((const float4*)(x + (size_t)row * DM))[tid];
    float s1 = v.x + v.y + v.z + v.w;
    float s2 = v.x*v.x + v.y*v.y + v.z*v.z + v.w*v.w;
#pragma unroll
    for (int o = 16; o; o >>= 1) {
        s1 += __shfl_xor_sync(0xffffffffu, s1, o);
        s2 += __shfl_xor_sync(0xffffffffu, s2, o);
    }
    if ((tid & 31) == 0) { sh1[tid >> 5] = s1; sh2[tid >> 5] = s2; }
    __syncthreads();
    if (tid < 32) {
        s1 = (tid < 8) ? sh1[tid] : 0.f;
        s2 = (tid < 8) ? sh2[tid] : 0.f;
#pragma unroll
        for (int o = 4; o; o >>= 1) {
            s1 += __shfl_xor_sync(0xffffffffu, s1, o);
            s2 += __shfl_xor_sync(0xffffffffu, s2, o);
        }
        if (tid == 0) { sh1[0] = s1; sh2[0] = s2; }
    }
    __syncthreads();
    const float mean = sh1[0] * (1.f / DM);
    const float var  = sh2[0] * (1.f / DM) - mean * mean;
    const float rstd = rsqrtf(var + 1e-5f);
    const float4 wv = ((const float4*)w)[tid];
    const float4 bv = ((const float4*)b)[tid];
    float o0 = (v.x - mean) * rstd * wv.x + bv.x;
    float o1 = (v.y - mean) * rstd * wv.y + bv.y;
    float o2 = (v.z - mean) * rstd * wv.z + bv.z;
    float o3 = (v.w - mean) * rstd * wv.w + bv.w;
    __nv_bfloat16 h0,h1,h2,h3,l0,l1,l2,l3;
    split_bf(o0,h0,l0); split_bf(o1,h1,l1); split_bf(o2,h2,l2); split_bf(o3,h3,l3);
    __nv_bfloat162 p;
    __nv_bfloat162* hp = (__nv_bfloat162*)(ohi + (size_t)row * DM) + tid * 2;
    __nv_bfloat162* lp = (__nv_bfloat162*)(olo + (size_t)row * DM) + tid * 2;
    p.x=h0; p.y=h1; hp[0]=p;  p.x=h2; p.y=h3; hp[1]=p;
    p.x=l0; p.y=l1; lp[0]=p;  p.x=l2; p.y=l3; lp[1]=p;
}

// ---------------- dt/softplus/dA ----------------
__global__ void dt_kernel(const float* __restrict__ dt_bias, const float* __restrict__ A_log)
{
    const int idx = blockIdx.x * blockDim.x + threadIdx.x;
    const int h = idx & (NH - 1);
    const int row = idx >> 5;
    const float raw = g_zx[(size_t)row * DIP + (DI + CDIM) + h] + dt_bias[h];
    const float dt = (raw > 20.f) ? raw : log1pf(expf(raw));
    const float A = -expf(A_log[h]);
    g_dt[idx] = dt;
    g_dA[idx] = expf(dt * A);
}

// ---------------- causal depthwise conv (d=4) + bias + SiLU ----------------
__global__ void conv_kernel(const float* __restrict__ cw, const float* __restrict__ cb)
{
    const int idx = blockIdx.x * blockDim.x + threadIdx.x;
    if (idx >= M_ROWS * CDIM) return;
    const int c = idx % CDIM;
    const int row = idx / CDIM;
    const int l = row & (SEQ - 1);
    const float w0 = cw[c*4+0], w1 = cw[c*4+1], w2 = cw[c*4+2], w3 = cw[c*4+3];
    float acc = cb[c];
    const size_t base = (size_t)row * DIP + DI + c;
    acc += g_zx[base] * w3;
    if (l >= 1) acc += g_zx[base - (size_t)DIP]     * w2;
    if (l >= 2) acc += g_zx[base - 2*(size_t)DIP]   * w1;
    if (l >= 3) acc += g_zx[base - 3*(size_t)DIP]   * w0;
    g_conv[idx] = acc * (1.f / (1.f + expf(-acc)));
}

// ---------------- selective scan, split over state-dim halves ----------------
__global__ __launch_bounds__(256, 1)
void scan_kernel(const float* __restrict__ Dp)
{
    const int bh   = blockIdx.x & 63;
    const int half = blockIdx.x >> 6;
    const int b = bh >> 5, h = bh & 31;
    const int tid = threadIdx.x;
    const int p = tid >> 2, g = tid & 3, nb = g * 8;

    __shared__ float sX[16][64], sB[16][32], sC[16][32], sY[16][64];
    __shared__ float sdt[16], sda[16];

    float st[8];
#pragma unroll
    for (int i = 0; i < 8; i++) st[i] = 0.f;

    const float Dh = Dp[h];
    const size_t rowbase = (size_t)b * SEQ;
    const int boff = DI + half * 32;
    const int coff = DI + NSTATE + half * 32;
    float* yout = half ? g_y2 : g_y;

    for (int l0 = 0; l0 < SEQ; l0 += 16) {
#pragma unroll
        for (int i = tid; i < 16 * 64; i += 256) {
            const int t = i >> 6, j = i & 63;
            sX[t][j] = g_conv[(rowbase + l0 + t) * (size_t)CDIM + h * 64 + j];
        }
#pragma unroll
        for (int i = tid; i < 16 * 32; i += 256) {
            const int t = i >> 5, j = i & 31;
            const size_t r = (rowbase + l0 + t) * (size_t)CDIM;
            sB[t][j] = g_conv[r + boff + j];
            sC[t][j] = g_conv[r + coff + j];
        }
        if (tid < 16) {
            const size_t r = rowbase + l0 + tid;
            sdt[tid] = g_dt[r * NH + h];
            sda[tid] = g_dA[r * NH + h];
        }
        __syncthreads();

#pragma unroll
        for (int t = 0; t < 16; t++) {
            const float xv  = sX[t][p];
            const float dtx = sdt[t] * xv;
            const float dav = sda[t];
            float acc = 0.f;
            const float4* Bv = (const float4*)&sB[t][nb];
            const float4* Cv = (const float4*)&sC[t][nb];
#pragma unroll
            for (int q = 0; q < 2; q++) {
                const float4 bq = Bv[q];
                const float4 cq = Cv[q];
                st[4*q+0] = dav * st[4*q+0] + dtx * bq.x; acc = fmaf(st[4*q+0], cq.x, acc);
                st[4*q+1] = dav * st[4*q+1] + dtx * bq.y; acc = fmaf(st[4*q+1], cq.y, acc);
                st[4*q+2] = dav * st[4*q+2] + dtx * bq.z; acc = fmaf(st[4*q+2], cq.z, acc);
                st[4*q+3] = dav * st[4*q+3] + dtx * bq.w; acc = fmaf(st[4*q+3], cq.w, acc);
            }
            acc += __shfl_xor_sync(0xffffffffu, acc, 1);
            acc += __shfl_xor_sync(0xffffffffu, acc, 2);
            if (g == 0) sY[t][p] = acc;
        }
        __syncthreads();

#pragma unroll
        for (int i = tid; i < 16 * 64; i += 256) {
            const int t = i >> 6, j = i & 63;
            const float skip = half ? 0.f : Dh * sX[t][j];
            yout[(rowbase + l0 + t) * (size_t)DI + h * 64 + j] = sY[t][j] + skip;
        }
        __syncthreads();
    }
}

// ---------------- gate (silu(z)) + RMSNorm -> bf16 hi/lo ----------------
__global__ void gaterms_kernel(const float* __restrict__ rw)
{
    __shared__ float sh[8];
    const int row = blockIdx.x;
    const int tid = threadIdx.x;
    const float* yr = g_y  + (size_t)row * DI;
    const float* y2 = g_y2 + (size_t)row * DI;
    const float* zr = g_zx + (size_t)row * DIP;
    float vals[8];
    float s2 = 0.f;
#pragma unroll
    for (int u = 0; u < 2; u++) {
        const int j = tid * 4 + u * 1024;
        const float4 yv = *(const float4*)(yr + j);
        const float4 y2v = *(const float4*)(y2 + j);
        const float4 zv = *(const float4*)(zr + j);
        const float y0 = yv.x + y2v.x, y1 = yv.y + y2v.y;
        const float y2s = yv.z + y2v.z, y3 = yv.w + y2v.w;
        const float g0 = y0 * (zv.x / (1.f + expf(-zv.x)));
        const float g1 = y1 * (zv.y / (1.f + expf(-zv.y)));
        const float g2 = y2s * (zv.z / (1.f + expf(-zv.z)));
        const float g3 = y3 * (zv.w / (1.f + expf(-zv.w)));
        vals[u*4+0] = g0; vals[u*4+1] = g1; vals[u*4+2] = g2; vals[u*4+3] = g3;
        s2 += g0*g0 + g1*g1 + g2*g2 + g3*g3;
    }
#pragma unroll
    for (int o = 16; o; o >>= 1) s2 += __shfl_xor_sync(0xffffffffu, s2, o);
    if ((tid & 31) == 0) sh[tid >> 5] = s2;
    __syncthreads();
    if (tid < 32) {
        s2 = (tid < 8) ? sh[tid] : 0.f;
#pragma unroll
        for (int o = 4; o; o >>= 1) s2 += __shfl_xor_sync(0xffffffffu, s2, o);
        if (tid == 0) sh[0] = s2;
    }
    __syncthreads();
    const float scale = rsqrtf(sh[0] * (1.f / DI) + 1e-5f);
#pragma unroll
    for (int u = 0; u < 2; u++) {
        const int j = tid * 4 + u * 1024;
        const float4 wv = *(const float4*)(rw + j);
        const float o0 = vals[u*4+0] * scale * wv.x;
        const float o1 = vals[u*4+1] * scale * wv.y;
        const float o2 = vals[u*4+2] * scale * wv.z;
        const float o3 = vals[u*4+3] * scale * wv.w;
        __nv_bfloat16 h0,h1,h2,h3,l0,l1,l2,l3;
        split_bf(o0,h0,l0); split_bf(o1,h1,l1); split_bf(o2,h2,l2); split_bf(o3,h3,l3);
        __nv_bfloat162 p;
        __nv_bfloat162* hp = (__nv_bfloat162*)(g_yhi + (size_t)row * DI + j);
        __nv_bfloat162* lp = (__nv_bfloat162*)(g_ylo + (size_t)row * DI + j);
        p.x=h0; p.y=h1; hp[0]=p;  p.x=h2; p.y=h3; hp[1]=p;
        p.x=l0; p.y=l1; lp[0]=p;  p.x=l2; p.y=l3; lp[1]=p;
    }
}

// ---------------- host launch ----------------
extern "C" void kernel_launch(void* const* d_in, const int* in_sizes, int n_in,
                              void* d_out, int out_size)
{
    const float* x       = (const float*)d_in[0];
    const float* ln_w    = (const float*)d_in[1];
    const float* ln_b    = (const float*)d_in[2];
    const float* in_proj = (const float*)d_in[3];
    const float* conv_w  = (const float*)d_in[4];
    const float* conv_b  = (const float*)d_in[5];
    const float* dt_bias = (const float*)d_in[6];
    const float* A_log   = (const float*)d_in[7];
    const float* Dvec    = (const float*)d_in[8];
    const float* rms_w   = (const float*)d_in[9];
    const float* out_w   = (const float*)d_in[10];
    float* out = (float*)d_out;

    float *p_h, *p_zx;
    __nv_bfloat16 *p_xhi, *p_xlo, *p_yhi, *p_ylo, *p_whi, *p_wlo;
    cudaGetSymbolAddress((void**)&p_h,   g_h);
    cudaGetSymbolAddress((void**)&p_zx,  g_zx);
    cudaGetSymbolAddress((void**)&p_xhi, g_xhi);
    cudaGetSymbolAddress((void**)&p_xlo, g_xlo);
    cudaGetSymbolAddress((void**)&p_yhi, g_yhi);
    cudaGetSymbolAddress((void**)&p_ylo, g_ylo);
    cudaGetSymbolAddress((void**)&p_whi, g_whi);
    cudaGetSymbolAddress((void**)&p_wlo, g_wlo);

    cudaFuncSetAttribute(gemm_mma, cudaFuncAttributeMaxDynamicSharedMemorySize, GEMM_SMEM);

    for (int i = 0; i < 2; i++) {
        const float* hin  = (i == 0) ? x   : p_h;
        float*       hout = (i == 0) ? p_h : out;

        ln_kernel<<<M_ROWS, 256>>>(hin, ln_w + i * DM, ln_b + i * DM, p_xhi, p_xlo);

        cvt_hilo<<<(DIP * DM / 4) / 256, 256>>>(in_proj + (size_t)i * DIP * DM, p_whi, p_wlo);

        gemm_mma<<<dim3((DIP + 127) / 128, M_ROWS / 256), 256, GEMM_SMEM>>>(
            p_xhi, p_xlo, p_whi, p_wlo, nullptr, p_zx, DIP, DM);

        dt_kernel<<<(M_ROWS * NH) / 256, 256>>>(dt_bias + i * NH, A_log + i * NH);

        conv_kernel<<<(M_ROWS * CDIM + 255) / 256, 256>>>(
            conv_w + (size_t)i * CDIM * 4, conv_b + (size_t)i * CDIM);

        scan_kernel<<<2 * BATCH * NH, 256>>>(Dvec + i * NH);

        gaterms_kernel<<<M_ROWS, 256>>>(rms_w + (size_t)i * DI);

        cvt_hilo<<<(DM * DI / 4) / 256, 256>>>(out_w + (size_t)i * DM * DI, p_whi, p_wlo);

        gemm_mma<<<dim3(DM / 128, M_ROWS / 256), 256, GEMM_SMEM>>>(
            p_yhi, p_ylo, p_whi, p_wlo, hin, hout, DM, DI);
    }
}

// round 10
// speedup vs baseline: 1.1441x; 1.1441x over previous
#include <cuda_runtime.h>
#include <cuda_fp16.h>
#include <math.h>
#include <stdint.h>

#define BATCH 2
#define SEQ   4096
#define DM    1024
#define DIP   4256
#define DI    2048
#define CDIM  2176
#define NH    32
#define HD    64
#define NSTATE 64
#define M_ROWS (BATCH*SEQ)   /* 8192 */

// ---------------- scratch (device globals; no allocations allowed) ----------------
__device__ float g_zx[(size_t)M_ROWS * DIP];
__device__ float g_conv[(size_t)M_ROWS * CDIM];
__device__ float g_dt[(size_t)M_ROWS * NH];
__device__ float g_dA[(size_t)M_ROWS * NH];
__device__ float g_y[(size_t)M_ROWS * DI];
__device__ float g_y2[(size_t)M_ROWS * DI];
__device__ float g_h[(size_t)M_ROWS * DM];
__device__ __half g_xh[(size_t)M_ROWS * DM];
__device__ __half g_xl[(size_t)M_ROWS * DM];
__device__ __half g_yh[(size_t)M_ROWS * DI];
__device__ __half g_yl[(size_t)M_ROWS * DI];
__device__ __half g_wh[(size_t)DIP * DM];

// ---------------- baseline-ISA PTX helpers ----------------
__device__ __forceinline__ uint32_t smem_u32_of(const void* p) {
    uint32_t a;
    asm("{ .reg .u64 t; cvta.to.shared.u64 t, %1; cvt.u32.u64 %0, t; }" : "=r"(a) : "l"(p));
    return a;
}
__device__ __forceinline__ void cp16(uint32_t dst, const void* src) {
    asm volatile("cp.async.cg.shared.global [%0], [%1], 16;" :: "r"(dst), "l"(src));
}
__device__ __forceinline__ void cp_commit() {
    asm volatile("cp.async.commit_group;" ::: "memory");
}
template<int N> __device__ __forceinline__ void cp_wait() {
    asm volatile("cp.async.wait_group %0;" :: "n"(N) : "memory");
}
__device__ __forceinline__ void ldsm_x4(uint32_t* r, uint32_t addr) {
    asm volatile("ldmatrix.sync.aligned.m8n8.x4.shared.b16 {%0,%1,%2,%3}, [%4];"
                 : "=r"(r[0]), "=r"(r[1]), "=r"(r[2]), "=r"(r[3]) : "r"(addr));
}
__device__ __forceinline__ void mma16816(float* d, const uint32_t* a, uint32_t b0, uint32_t b1) {
    asm volatile("mma.sync.aligned.m16n8k16.row.col.f32.f16.f16.f32 "
                 "{%0,%1,%2,%3}, {%4,%5,%6,%7}, {%8,%9}, {%0,%1,%2,%3};"
                 : "+f"(d[0]), "+f"(d[1]), "+f"(d[2]), "+f"(d[3])
                 : "r"(a[0]), "r"(a[1]), "r"(a[2]), "r"(a[3]), "r"(b0), "r"(b1));
}
__device__ __forceinline__ void split_h(float v, __half& h, __half& l) {
    h = __float2half_rn(v);
    l = __float2half_rn(v - __half2float(h));
}

// ---------------- weight fp32 -> fp16 ----------------
__global__ void cvt_f16(const float* __restrict__ s, __half* __restrict__ o)
{
    const size_t idx = (size_t)blockIdx.x * blockDim.x + threadIdx.x;
    const float4 v = ((const float4*)s)[idx];
    __half2 a, b;
    a.x = __float2half_rn(v.x); a.y = __float2half_rn(v.y);
    b.x = __float2half_rn(v.z); b.y = __float2half_rn(v.w);
    ((__half2*)o)[idx*2] = a; ((__half2*)o)[idx*2+1] = b;
}

// ---------------- HMMA fp16 2-term GEMM ----------------
// C[M,Nn] = (Ah+Al)[M,K] * W[Nn,K]^T (+Res). A split fp16 hi/lo (exact), W single fp16.
// CTA 256x128, 8 warps (4x2), warp tile 64x64, BK=32, 3-stage cp.async.
#define ROWB   80
#define OFF_AH 0
#define OFF_AL (256 * ROWB)               /* 20480 */
#define OFF_B  (512 * ROWB)               /* 40960 */
#define STAGE  (OFF_B + 128 * ROWB)       /* 51200 */
#define NSTAGE 3
#define GEMM_SMEM (NSTAGE * STAGE)        /* 153600 */

__global__ __launch_bounds__(256, 1)
void gemm_mma(const __half* __restrict__ Ahi, const __half* __restrict__ Alo,
              const __half* __restrict__ W,
              const float* __restrict__ Res, float* __restrict__ C,
              int Nn, int K)
{
    extern __shared__ char smem[];
    const uint32_t sb = smem_u32_of(smem);
    const int tid  = threadIdx.x;
    const int wid  = tid >> 5;
    const int lane = tid & 31;
    const int bm = blockIdx.y * 256;
    const int bn = blockIdx.x * 128;
    const int wm = wid >> 1;
    const int wn = wid & 1;
    const int NC = K >> 5;

    float acc[4][8][4];
#pragma unroll
    for (int i = 0; i < 4; i++)
#pragma unroll
        for (int j = 0; j < 8; j++)
#pragma unroll
            for (int q = 0; q < 4; q++) acc[i][j][q] = 0.f;

    const int ra = tid;
    const int rb = tid >> 1;
    const int lc = (tid & 1) * 2;
    int brow = bn + rb; if (brow >= Nn) brow = Nn - 1;
    const __half* pah = Ahi + (size_t)(bm + ra) * K;
    const __half* pal = Alo + (size_t)(bm + ra) * K;
    const __half* pb  = W   + (size_t)brow * K;

#define LOAD_CHUNK(c) do {                                            \
    const uint32_t s0 = sb + ((c) % NSTAGE) * STAGE;                  \
    const int kof = (c) * 32;                                         \
    const uint32_t sa = s0 + ra * ROWB;                               \
    _Pragma("unroll")                                                 \
    for (int q = 0; q < 4; q++) {                                     \
        cp16(sa + OFF_AH + q * 16, pah + kof + q * 8);                \
        cp16(sa + OFF_AL + q * 16, pal + kof + q * 8);                \
    }                                                                 \
    const uint32_t sbr = s0 + rb * ROWB;                              \
    _Pragma("unroll")                                                 \
    for (int q = 0; q < 2; q++) {                                     \
        const int ch = lc + q;                                        \
        cp16(sbr + OFF_B + ch * 16, pb + kof + ch * 8);               \
    }                                                                 \
    cp_commit();                                                      \
} while (0)

    LOAD_CHUNK(0);
    if (NC > 1) LOAD_CHUNK(1);

    const int a_rb  = wm * 64 + (lane & 15);
    const int a_chk = (lane >> 4) * 16;
    const int b_rb  = wn * 64 + ((lane >> 4) << 3) + (lane & 7);
    const int b_chk = ((lane >> 3) & 1) * 16;

    for (int c = 0; c < NC; c++) {
        if (c + 1 < NC) cp_wait<1>(); else cp_wait<0>();
        __syncthreads();
        if (c + 2 < NC) LOAD_CHUNK(c + 2);

        const uint32_t sbuf = sb + (c % NSTAGE) * STAGE;

#pragma unroll
        for (int ks = 0; ks < 2; ks++) {
            uint32_t ah[4][4], al[4][4];
#pragma unroll
            for (int im = 0; im < 4; im++) {
                const uint32_t addr = sbuf + (a_rb + im * 16) * ROWB + ks * 32 + a_chk;
                ldsm_x4(ah[im], addr + OFF_AH);
                ldsm_x4(al[im], addr + OFF_AL);
            }
#pragma unroll
            for (int g = 0; g < 4; g++) {
                uint32_t bb[4];
                const uint32_t addr = sbuf + (b_rb + g * 16) * ROWB + ks * 32 + b_chk;
                ldsm_x4(bb, addr + OFF_B);
                // term 1: Ah*B — 8 independent accumulators
#pragma unroll
                for (int im = 0; im < 4; im++)
#pragma unroll
                    for (int hf = 0; hf < 2; hf++)
                        mma16816(acc[im][g*2+hf], ah[im], bb[hf*2], bb[hf*2+1]);
                // term 2: Al*B
#pragma unroll
                for (int im = 0; im < 4; im++)
#pragma unroll
                    for (int hf = 0; hf < 2; hf++)
                        mma16816(acc[im][g*2+hf], al[im], bb[hf*2], bb[hf*2+1]);
            }
        }
    }
#undef LOAD_CHUNK

    // epilogue
#pragma unroll
    for (int im = 0; im < 4; im++) {
        const int r0 = bm + wm * 64 + im * 16 + (lane >> 2);
#pragma unroll
        for (int j = 0; j < 8; j++) {
            const int n0 = bn + wn * 64 + j * 8;
            if (n0 < Nn) {
                const int cc = n0 + (lane & 3) * 2;
                float2 v0 = make_float2(acc[im][j][0], acc[im][j][1]);
                float2 v1 = make_float2(acc[im][j][2], acc[im][j][3]);
                if (Res) {
                    const float2 r0v = *(const float2*)&Res[(size_t)r0 * Nn + cc];
                    const float2 r1v = *(const float2*)&Res[(size_t)(r0 + 8) * Nn + cc];
                    v0.x += r0v.x; v0.y += r0v.y;
                    v1.x += r1v.x; v1.y += r1v.y;
                }
                *(float2*)&C[(size_t)r0 * Nn + cc] = v0;
                *(float2*)&C[(size_t)(r0 + 8) * Nn + cc] = v1;
            }
        }
    }
}

// ---------------- LayerNorm -> fp16 hi/lo ----------------
__global__ void ln_kernel(const float* __restrict__ x, const float* __restrict__ w,
                          const float* __restrict__ b,
                          __half* __restrict__ ohi, __half* __restrict__ olo)
{
    __shared__ float sh1[8], sh2[8];
    const int row = blockIdx.x;
    const int tid = threadIdx.x;
    const float4 v = ((const float4*)(x + (size_t)row * DM))[tid];
    float s1 = v.x + v.y + v.z + v.w;
    float s2 = v.x*v.x + v.y*v.y + v.z*v.z + v.w*v.w;
#pragma unroll
    for (int o = 16; o; o >>= 1) {
        s1 += __shfl_xor_sync(0xffffffffu, s1, o);
        s2 += __shfl_xor_sync(0xffffffffu, s2, o);
    }
    if ((tid & 31) == 0) { sh1[tid >> 5] = s1; sh2[tid >> 5] = s2; }
    __syncthreads();
    if (tid < 32) {
        s1 = (tid < 8) ? sh1[tid] : 0.f;
        s2 = (tid < 8) ? sh2[tid] : 0.f;
#pragma unroll
        for (int o = 4; o; o >>= 1) {
            s1 += __shfl_xor_sync(0xffffffffu, s1, o);
            s2 += __shfl_xor_sync(0xffffffffu, s2, o);
        }
        if (tid == 0) { sh1[0] = s1; sh2[0] = s2; }
    }
    __syncthreads();
    const float mean = sh1[0] * (1.f / DM);
    const float var  = sh2[0] * (1.f / DM) - mean * mean;
    const float rstd = rsqrtf(var + 1e-5f);
    const float4 wv = ((const float4*)w)[tid];
    const float4 bv = ((const float4*)b)[tid];
    float o0 = (v.x - mean) * rstd * wv.x + bv.x;
    float o1 = (v.y - mean) * rstd * wv.y + bv.y;
    float o2 = (v.z - mean) * rstd * wv.z + bv.z;
    float o3 = (v.w - mean) * rstd * wv.w + bv.w;
    __half h0,h1,h2,h3,l0,l1,l2,l3;
    split_h(o0,h0,l0); split_h(o1,h1,l1); split_h(o2,h2,l2); split_h(o3,h3,l3);
    __half2 p;
    __half2* hp = (__half2*)(ohi + (size_t)row * DM) + tid * 2;
    __half2* lp = (__half2*)(olo + (size_t)row * DM) + tid * 2;
    p.x=h0; p.y=h1; hp[0]=p;  p.x=h2; p.y=h3; hp[1]=p;
    p.x=l0; p.y=l1; lp[0]=p;  p.x=l2; p.y=l3; lp[1]=p;
}

// ---------------- dt/softplus/dA ----------------
__global__ void dt_kernel(const float* __restrict__ dt_bias, const float* __restrict__ A_log)
{
    const int idx = blockIdx.x * blockDim.x + threadIdx.x;
    const int h = idx & (NH - 1);
    const int row = idx >> 5;
    const float raw = g_zx[(size_t)row * DIP + (DI + CDIM) + h] + dt_bias[h];
    const float dt = (raw > 20.f) ? raw : log1pf(expf(raw));
    const float A = -expf(A_log[h]);
    g_dt[idx] = dt;
    g_dA[idx] = expf(dt * A);
}

// ---------------- causal depthwise conv (d=4) + bias + SiLU ----------------
__global__ void conv_kernel(const float* __restrict__ cw, const float* __restrict__ cb)
{
    const int idx = blockIdx.x * blockDim.x + threadIdx.x;
    if (idx >= M_ROWS * CDIM) return;
    const int c = idx % CDIM;
    const int row = idx / CDIM;
    const int l = row & (SEQ - 1);
    const float w0 = cw[c*4+0], w1 = cw[c*4+1], w2 = cw[c*4+2], w3 = cw[c*4+3];
    float acc = cb[c];
    const size_t base = (size_t)row * DIP + DI + c;
    acc += g_zx[base] * w3;
    if (l >= 1) acc += g_zx[base - (size_t)DIP]     * w2;
    if (l >= 2) acc += g_zx[base - 2*(size_t)DIP]   * w1;
    if (l >= 3) acc += g_zx[base - 3*(size_t)DIP]   * w0;
    g_conv[idx] = acc * (1.f / (1.f + expf(-acc)));
}

// ---------------- selective scan, split over state-dim halves ----------------
__global__ __launch_bounds__(256, 1)
void scan_kernel(const float* __restrict__ Dp)
{
    const int bh   = blockIdx.x & 63;
    const int half = blockIdx.x >> 6;
    const int b = bh >> 5, h = bh & 31;
    const int tid = threadIdx.x;
    const int p = tid >> 2, g = tid & 3, nb = g * 8;

    __shared__ float sX[16][64], sB[16][32], sC[16][32], sY[16][64];
    __shared__ float sdt[16], sda[16];

    float st[8];
#pragma unroll
    for (int i = 0; i < 8; i++) st[i] = 0.f;

    const float Dh = Dp[h];
    const size_t rowbase = (size_t)b * SEQ;
    const int boff = DI + half * 32;
    const int coff = DI + NSTATE + half * 32;
    float* yout = half ? g_y2 : g_y;

    for (int l0 = 0; l0 < SEQ; l0 += 16) {
#pragma unroll
        for (int i = tid; i < 16 * 64; i += 256) {
            const int t = i >> 6, j = i & 63;
            sX[t][j] = g_conv[(rowbase + l0 + t) * (size_t)CDIM + h * 64 + j];
        }
#pragma unroll
        for (int i = tid; i < 16 * 32; i += 256) {
            const int t = i >> 5, j = i & 31;
            const size_t r = (rowbase + l0 + t) * (size_t)CDIM;
            sB[t][j] = g_conv[r + boff + j];
            sC[t][j] = g_conv[r + coff + j];
        }
        if (tid < 16) {
            const size_t r = rowbase + l0 + tid;
            sdt[tid] = g_dt[r * NH + h];
            sda[tid] = g_dA[r * NH + h];
        }
        __syncthreads();

#pragma unroll
        for (int t = 0; t < 16; t++) {
            const float xv  = sX[t][p];
            const float dtx = sdt[t] * xv;
            const float dav = sda[t];
            float acc = 0.f;
            const float4* Bv = (const float4*)&sB[t][nb];
            const float4* Cv = (const float4*)&sC[t][nb];
#pragma unroll
            for (int q = 0; q < 2; q++) {
                const float4 bq = Bv[q];
                const float4 cq = Cv[q];
                st[4*q+0] = dav * st[4*q+0] + dtx * bq.x; acc = fmaf(st[4*q+0], cq.x, acc);
                st[4*q+1] = dav * st[4*q+1] + dtx * bq.y; acc = fmaf(st[4*q+1], cq.y, acc);
                st[4*q+2] = dav * st[4*q+2] + dtx * bq.z; acc = fmaf(st[4*q+2], cq.z, acc);
                st[4*q+3] = dav * st[4*q+3] + dtx * bq.w; acc = fmaf(st[4*q+3], cq.w, acc);
            }
            acc += __shfl_xor_sync(0xffffffffu, acc, 1);
            acc += __shfl_xor_sync(0xffffffffu, acc, 2);
            if (g == 0) sY[t][p] = acc;
        }
        __syncthreads();

#pragma unroll
        for (int i = tid; i < 16 * 64; i += 256) {
            const int t = i >> 6, j = i & 63;
            const float skip = half ? 0.f : Dh * sX[t][j];
            yout[(rowbase + l0 + t) * (size_t)DI + h * 64 + j] = sY[t][j] + skip;
        }
        __syncthreads();
    }
}

// ---------------- gate (silu(z)) + RMSNorm -> fp16 hi/lo ----------------
__global__ void gaterms_kernel(const float* __restrict__ rw)
{
    __shared__ float sh[8];
    const int row = blockIdx.x;
    const int tid = threadIdx.x;
    const float* yr = g_y  + (size_t)row * DI;
    const float* y2 = g_y2 + (size_t)row * DI;
    const float* zr = g_zx + (size_t)row * DIP;
    float vals[8];
    float s2 = 0.f;
#pragma unroll
    for (int u = 0; u < 2; u++) {
        const int j = tid * 4 + u * 1024;
        const float4 yv = *(const float4*)(yr + j);
        const float4 y2v = *(const float4*)(y2 + j);
        const float4 zv = *(const float4*)(zr + j);
        const float y0 = yv.x + y2v.x, y1 = yv.y + y2v.y;
        const float y2s = yv.z + y2v.z, y3 = yv.w + y2v.w;
        const float g0 = y0 * (zv.x / (1.f + expf(-zv.x)));
        const float g1 = y1 * (zv.y / (1.f + expf(-zv.y)));
        const float g2 = y2s * (zv.z / (1.f + expf(-zv.z)));
        const float g3 = y3 * (zv.w / (1.f + expf(-zv.w)));
        vals[u*4+0] = g0; vals[u*4+1] = g1; vals[u*4+2] = g2; vals[u*4+3] = g3;
        s2 += g0*g0 + g1*g1 + g2*g2 + g3*g3;
    }
#pragma unroll
    for (int o = 16; o; o >>= 1) s2 += __shfl_xor_sync(0xffffffffu, s2, o);
    if ((tid & 31) == 0) sh[tid >> 5] = s2;
    __syncthreads();
    if (tid < 32) {
        s2 = (tid < 8) ? sh[tid] : 0.f;
#pragma unroll
        for (int o = 4; o; o >>= 1) s2 += __shfl_xor_sync(0xffffffffu, s2, o);
        if (tid == 0) sh[0] = s2;
    }
    __syncthreads();
    const float scale = rsqrtf(sh[0] * (1.f / DI) + 1e-5f);
#pragma unroll
    for (int u = 0; u < 2; u++) {
        const int j = tid * 4 + u * 1024;
        const float4 wv = *(const float4*)(rw + j);
        const float o0 = vals[u*4+0] * scale * wv.x;
        const float o1 = vals[u*4+1] * scale * wv.y;
        const float o2 = vals[u*4+2] * scale * wv.z;
        const float o3 = vals[u*4+3] * scale * wv.w;
        __half h0,h1,h2,h3,l0,l1,l2,l3;
        split_h(o0,h0,l0); split_h(o1,h1,l1); split_h(o2,h2,l2); split_h(o3,h3,l3);
        __half2 p;
        __half2* hp = (__half2*)(g_yh + (size_t)row * DI + j);
        __half2* lp = (__half2*)(g_yl + (size_t)row * DI + j);
        p.x=h0; p.y=h1; hp[0]=p;  p.x=h2; p.y=h3; hp[1]=p;
        p.x=l0; p.y=l1; lp[0]=p;  p.x=l2; p.y=l3; lp[1]=p;
    }
}

// ---------------- host launch ----------------
extern "C" void kernel_launch(void* const* d_in, const int* in_sizes, int n_in,
                              void* d_out, int out_size)
{
    const float* x       = (const float*)d_in[0];
    const float* ln_w    = (const float*)d_in[1];
    const float* ln_b    = (const float*)d_in[2];
    const float* in_proj = (const float*)d_in[3];
    const float* conv_w  = (const float*)d_in[4];
    const float* conv_b  = (const float*)d_in[5];
    const float* dt_bias = (const float*)d_in[6];
    const float* A_log   = (const float*)d_in[7];
    const float* Dvec    = (const float*)d_in[8];
    const float* rms_w   = (const float*)d_in[9];
    const float* out_w   = (const float*)d_in[10];
    float* out = (float*)d_out;

    float *p_h, *p_zx;
    __half *p_xh, *p_xl, *p_yh, *p_yl, *p_wh;
    cudaGetSymbolAddress((void**)&p_h,  g_h);
    cudaGetSymbolAddress((void**)&p_zx, g_zx);
    cudaGetSymbolAddress((void**)&p_xh, g_xh);
    cudaGetSymbolAddress((void**)&p_xl, g_xl);
    cudaGetSymbolAddress((void**)&p_yh, g_yh);
    cudaGetSymbolAddress((void**)&p_yl, g_yl);
    cudaGetSymbolAddress((void**)&p_wh, g_wh);

    cudaFuncSetAttribute(gemm_mma, cudaFuncAttributeMaxDynamicSharedMemorySize, GEMM_SMEM);

    for (int i = 0; i < 2; i++) {
        const float* hin  = (i == 0) ? x   : p_h;
        float*       hout = (i == 0) ? p_h : out;

        ln_kernel<<<M_ROWS, 256>>>(hin, ln_w + i * DM, ln_b + i * DM, p_xh, p_xl);

        cvt_f16<<<(DIP * DM / 4) / 256, 256>>>(in_proj + (size_t)i * DIP * DM, p_wh);

        gemm_mma<<<dim3((DIP + 127) / 128, M_ROWS / 256), 256, GEMM_SMEM>>>(
            p_xh, p_xl, p_wh, nullptr, p_zx, DIP, DM);

        dt_kernel<<<(M_ROWS * NH) / 256, 256>>>(dt_bias + i * NH, A_log + i * NH);

        conv_kernel<<<(M_ROWS * CDIM + 255) / 256, 256>>>(
            conv_w + (size_t)i * CDIM * 4, conv_b + (size_t)i * CDIM);

        scan_kernel<<<2 * BATCH * NH, 256>>>(Dvec + i * NH);

        gaterms_kernel<<<M_ROWS, 256>>>(rms_w + (size_t)i * DI);

        cvt_f16<<<(DM * DI / 4) / 256, 256>>>(out_w + (size_t)i * DM * DI, p_wh);

        gemm_mma<<<dim3(DM / 128, M_ROWS / 256), 256, GEMM_SMEM>>>(
            p_yh, p_yl, p_wh, hin, hout, DM, DI);
    }
}

// round 14
// speedup vs baseline: 1.1476x; 1.0031x over previous
#include <cuda_runtime.h>
#include <cuda_fp16.h>
#include <math.h>
#include <stdint.h>

#define BATCH 2
#define SEQ   4096
#define DM    1024
#define DIP   4256
#define DI    2048
#define CDIM  2176
#define NH    32
#define HD    64
#define NSTATE 64
#define M_ROWS (BATCH*SEQ)   /* 8192 */

typedef unsigned long long ull;

// ---------------- scratch (device globals; no allocations allowed) ----------------
__device__ float g_zx[(size_t)M_ROWS * DIP];
__device__ float g_conv[(size_t)M_ROWS * CDIM];
__device__ float g_dt[(size_t)M_ROWS * NH];
__device__ float g_dA[(size_t)M_ROWS * NH];
__device__ float g_y[(size_t)M_ROWS * DI];
__device__ float g_y2[(size_t)M_ROWS * DI];
__device__ float g_h[(size_t)M_ROWS * DM];
__device__ __half g_xh[(size_t)M_ROWS * DM];
__device__ __half g_xl[(size_t)M_ROWS * DM];
__device__ __half g_yh[(size_t)M_ROWS * DI];
__device__ __half g_yl[(size_t)M_ROWS * DI];
__device__ __half g_wh[(size_t)DIP * DM];

// ---------------- baseline-ISA PTX helpers ----------------
__device__ __forceinline__ uint32_t smem_u32_of(const void* p) {
    uint32_t a;
    asm("{ .reg .u64 t; cvta.to.shared.u64 t, %1; cvt.u32.u64 %0, t; }" : "=r"(a) : "l"(p));
    return a;
}
__device__ __forceinline__ void cp16(uint32_t dst, const void* src) {
    asm volatile("cp.async.cg.shared.global [%0], [%1], 16;" :: "r"(dst), "l"(src));
}
__device__ __forceinline__ void cp_commit() {
    asm volatile("cp.async.commit_group;" ::: "memory");
}
template<int N> __device__ __forceinline__ void cp_wait() {
    asm volatile("cp.async.wait_group %0;" :: "n"(N) : "memory");
}
__device__ __forceinline__ void ldsm_x4(uint32_t* r, uint32_t addr) {
    asm volatile("ldmatrix.sync.aligned.m8n8.x4.shared.b16 {%0,%1,%2,%3}, [%4];"
                 : "=r"(r[0]), "=r"(r[1]), "=r"(r[2]), "=r"(r[3]) : "r"(addr));
}
__device__ __forceinline__ void mma16816(float* d, const uint32_t* a, uint32_t b0, uint32_t b1) {
    asm volatile("mma.sync.aligned.m16n8k16.row.col.f32.f16.f16.f32 "
                 "{%0,%1,%2,%3}, {%4,%5,%6,%7}, {%8,%9}, {%0,%1,%2,%3};"
                 : "+f"(d[0]), "+f"(d[1]), "+f"(d[2]), "+f"(d[3])
                 : "r"(a[0]), "r"(a[1]), "r"(a[2]), "r"(a[3]), "r"(b0), "r"(b1));
}
__device__ __forceinline__ void split_h(float v, __half& h, __half& l) {
    h = __float2half_rn(v);
    l = __float2half_rn(v - __half2float(h));
}
// packed f32x2 fma (exact IEEE fp32 per element)
__device__ __forceinline__ ull ffma2(ull a, ull b, ull c) {
    ull d;
    asm("fma.rn.f32x2 %0, %1, %2, %3;" : "=l"(d) : "l"(a), "l"(b), "l"(c));
    return d;
}
__device__ __forceinline__ ull dup2(float x) {
    ull d;
    asm("mov.b64 %0, {%1, %1};" : "=l"(d) : "r"(__float_as_int(x)));
    return d;
}
__device__ __forceinline__ float hsum2(ull a) {
    float lo, hi;
    asm("mov.b64 {%0, %1}, %2;" : "=f"(lo), "=f"(hi) : "l"(a));
    return lo + hi;
}

// ---------------- weight fp32 -> fp16 ----------------
__global__ void cvt_f16(const float* __restrict__ s, __half* __restrict__ o)
{
    const size_t idx = (size_t)blockIdx.x * blockDim.x + threadIdx.x;
    const float4 v = ((const float4*)s)[idx];
    __half2 a, b;
    a.x = __float2half_rn(v.x); a.y = __float2half_rn(v.y);
    b.x = __float2half_rn(v.z); b.y = __float2half_rn(v.w);
    ((__half2*)o)[idx*2] = a; ((__half2*)o)[idx*2+1] = b;
}

// ---------------- HMMA fp16 2-term GEMM (unchanged from R10) ----------------
#define ROWB   80
#define OFF_AH 0
#define OFF_AL (256 * ROWB)
#define OFF_B  (512 * ROWB)
#define STAGE  (OFF_B + 128 * ROWB)
#define NSTAGE 3
#define GEMM_SMEM (NSTAGE * STAGE)

__global__ __launch_bounds__(256, 1)
void gemm_mma(const __half* __restrict__ Ahi, const __half* __restrict__ Alo,
              const __half* __restrict__ W,
              const float* __restrict__ Res, float* __restrict__ C,
              int Nn, int K)
{
    extern __shared__ char smem[];
    const uint32_t sb = smem_u32_of(smem);
    const int tid  = threadIdx.x;
    const int wid  = tid >> 5;
    const int lane = tid & 31;
    const int bm = blockIdx.y * 256;
    const int bn = blockIdx.x * 128;
    const int wm = wid >> 1;
    const int wn = wid & 1;
    const int NC = K >> 5;

    float acc[4][8][4];
#pragma unroll
    for (int i = 0; i < 4; i++)
#pragma unroll
        for (int j = 0; j < 8; j++)
#pragma unroll
            for (int q = 0; q < 4; q++) acc[i][j][q] = 0.f;

    const int ra = tid;
    const int rb = tid >> 1;
    const int lc = (tid & 1) * 2;
    int brow = bn + rb; if (brow >= Nn) brow = Nn - 1;
    const __half* pah = Ahi + (size_t)(bm + ra) * K;
    const __half* pal = Alo + (size_t)(bm + ra) * K;
    const __half* pb  = W   + (size_t)brow * K;

#define LOAD_CHUNK(c) do {                                            \
    const uint32_t s0 = sb + ((c) % NSTAGE) * STAGE;                  \
    const int kof = (c) * 32;                                         \
    const uint32_t sa = s0 + ra * ROWB;                               \
    _Pragma("unroll")                                                 \
    for (int q = 0; q < 4; q++) {                                     \
        cp16(sa + OFF_AH + q * 16, pah + kof + q * 8);                \
        cp16(sa + OFF_AL + q * 16, pal + kof + q * 8);                \
    }                                                                 \
    const uint32_t sbr = s0 + rb * ROWB;                              \
    _Pragma("unroll")                                                 \
    for (int q = 0; q < 2; q++) {                                     \
        const int ch = lc + q;                                        \
        cp16(sbr + OFF_B + ch * 16, pb + kof + ch * 8);               \
    }                                                                 \
    cp_commit();                                                      \
} while (0)

    LOAD_CHUNK(0);
    if (NC > 1) LOAD_CHUNK(1);

    const int a_rb  = wm * 64 + (lane & 15);
    const int a_chk = (lane >> 4) * 16;
    const int b_rb  = wn * 64 + ((lane >> 4) << 3) + (lane & 7);
    const int b_chk = ((lane >> 3) & 1) * 16;

    for (int c = 0; c < NC; c++) {
        if (c + 1 < NC) cp_wait<1>(); else cp_wait<0>();
        __syncthreads();
        if (c + 2 < NC) LOAD_CHUNK(c + 2);

        const uint32_t sbuf = sb + (c % NSTAGE) * STAGE;

#pragma unroll
        for (int ks = 0; ks < 2; ks++) {
            uint32_t ah[4][4], al[4][4];
#pragma unroll
            for (int im = 0; im < 4; im++) {
                const uint32_t addr = sbuf + (a_rb + im * 16) * ROWB + ks * 32 + a_chk;
                ldsm_x4(ah[im], addr + OFF_AH);
                ldsm_x4(al[im], addr + OFF_AL);
            }
#pragma unroll
            for (int g = 0; g < 4; g++) {
                uint32_t bb[4];
                const uint32_t addr = sbuf + (b_rb + g * 16) * ROWB + ks * 32 + b_chk;
                ldsm_x4(bb, addr + OFF_B);
#pragma unroll
                for (int im = 0; im < 4; im++)
#pragma unroll
                    for (int hf = 0; hf < 2; hf++)
                        mma16816(acc[im][g*2+hf], ah[im], bb[hf*2], bb[hf*2+1]);
#pragma unroll
                for (int im = 0; im < 4; im++)
#pragma unroll
                    for (int hf = 0; hf < 2; hf++)
                        mma16816(acc[im][g*2+hf], al[im], bb[hf*2], bb[hf*2+1]);
            }
        }
    }
#undef LOAD_CHUNK

#pragma unroll
    for (int im = 0; im < 4; im++) {
        const int r0 = bm + wm * 64 + im * 16 + (lane >> 2);
#pragma unroll
        for (int j = 0; j < 8; j++) {
            const int n0 = bn + wn * 64 + j * 8;
            if (n0 < Nn) {
                const int cc = n0 + (lane & 3) * 2;
                float2 v0 = make_float2(acc[im][j][0], acc[im][j][1]);
                float2 v1 = make_float2(acc[im][j][2], acc[im][j][3]);
                if (Res) {
                    const float2 r0v = *(const float2*)&Res[(size_t)r0 * Nn + cc];
                    const float2 r1v = *(const float2*)&Res[(size_t)(r0 + 8) * Nn + cc];
                    v0.x += r0v.x; v0.y += r0v.y;
                    v1.x += r1v.x; v1.y += r1v.y;
                }
                *(float2*)&C[(size_t)r0 * Nn + cc] = v0;
                *(float2*)&C[(size_t)(r0 + 8) * Nn + cc] = v1;
            }
        }
    }
}

// ---------------- LayerNorm -> fp16 hi/lo ----------------
__global__ void ln_kernel(const float* __restrict__ x, const float* __restrict__ w,
                          const float* __restrict__ b,
                          __half* __restrict__ ohi, __half* __restrict__ olo)
{
    __shared__ float sh1[8], sh2[8];
    const int row = blockIdx.x;
    const int tid = threadIdx.x;
    const float4 v = ((const float4*)(x + (size_t)row * DM))[tid];
    float s1 = v.x + v.y + v.z + v.w;
    float s2 = v.x*v.x + v.y*v.y + v.z*v.z + v.w*v.w;
#pragma unroll
    for (int o = 16; o; o >>= 1) {
        s1 += __shfl_xor_sync(0xffffffffu, s1, o);
        s2 += __shfl_xor_sync(0xffffffffu, s2, o);
    }
    if ((tid & 31) == 0) { sh1[tid >> 5] = s1; sh2[tid >> 5] = s2; }
    __syncthreads();
    if (tid < 32) {
        s1 = (tid < 8) ? sh1[tid] : 0.f;
        s2 = (tid < 8) ? sh2[tid] : 0.f;
#pragma unroll
        for (int o = 4; o; o >>= 1) {
            s1 += __shfl_xor_sync(0xffffffffu, s1, o);
            s2 += __shfl_xor_sync(0xffffffffu, s2, o);
        }
        if (tid == 0) { sh1[0] = s1; sh2[0] = s2; }
    }
    __syncthreads();
    const float mean = sh1[0] * (1.f / DM);
    const float var  = sh2[0] * (1.f / DM) - mean * mean;
    const float rstd = rsqrtf(var + 1e-5f);
    const float4 wv = ((const float4*)w)[tid];
    const float4 bv = ((const float4*)b)[tid];
    float o0 = (v.x - mean) * rstd * wv.x + bv.x;
    float o1 = (v.y - mean) * rstd * wv.y + bv.y;
    float o2 = (v.z - mean) * rstd * wv.z + bv.z;
    float o3 = (v.w - mean) * rstd * wv.w + bv.w;
    __half h0,h1,h2,h3,l0,l1,l2,l3;
    split_h(o0,h0,l0); split_h(o1,h1,l1); split_h(o2,h2,l2); split_h(o3,h3,l3);
    __half2 p;
    __half2* hp = (__half2*)(ohi + (size_t)row * DM) + tid * 2;
    __half2* lp = (__half2*)(olo + (size_t)row * DM) + tid * 2;
    p.x=h0; p.y=h1; hp[0]=p;  p.x=h2; p.y=h3; hp[1]=p;
    p.x=l0; p.y=l1; lp[0]=p;  p.x=l2; p.y=l3; lp[1]=p;
}

// ---------------- dt/softplus/dA ----------------
__global__ void dt_kernel(const float* __restrict__ dt_bias, const float* __restrict__ A_log)
{
    const int idx = blockIdx.x * blockDim.x + threadIdx.x;
    const int h = idx & (NH - 1);
    const int row = idx >> 5;
    const float raw = g_zx[(size_t)row * DIP + (DI + CDIM) + h] + dt_bias[h];
    const float dt = (raw > 20.f) ? raw : log1pf(expf(raw));
    const float A = -expf(A_log[h]);
    g_dt[idx] = dt;
    g_dA[idx] = expf(dt * A);
}

// ---------------- causal depthwise conv (d=4) + bias + SiLU ----------------
__global__ void conv_kernel(const float* __restrict__ cw, const float* __restrict__ cb)
{
    const int idx = blockIdx.x * blockDim.x + threadIdx.x;
    if (idx >= M_ROWS * CDIM) return;
    const int c = idx % CDIM;
    const int row = idx / CDIM;
    const int l = row & (SEQ - 1);
    const float w0 = cw[c*4+0], w1 = cw[c*4+1], w2 = cw[c*4+2], w3 = cw[c*4+3];
    float acc = cb[c];
    const size_t base = (size_t)row * DIP + DI + c;
    acc += g_zx[base] * w3;
    if (l >= 1) acc += g_zx[base - (size_t)DIP]     * w2;
    if (l >= 2) acc += g_zx[base - 2*(size_t)DIP]   * w1;
    if (l >= 3) acc += g_zx[base - 3*(size_t)DIP]   * w0;
    g_conv[idx] = acc * (1.f / (1.f + expf(-acc)));
}

// ---------------- selective scan v2 ----------------
// Split over state-dim halves (grid=128). cp.async double-buffered chunk tiles,
// packed f32x2 state math, cross-thread reduction deferred to chunk epilogue.
__global__ __launch_bounds__(256, 1)
void scan_kernel(const float* __restrict__ Dp)
{
    const int bh   = blockIdx.x & 63;
    const int half = blockIdx.x >> 6;
    const int b = bh >> 5, h = bh & 31;
    const int tid = threadIdx.x;
    const int p = tid >> 2, g = tid & 3, nb = g * 8;

    __shared__ float sX[2][16][64], sB[2][16][32], sC[2][16][32];
    __shared__ float sdt[2][16], sda[2][16];
    __shared__ float sY[16][64];

    const uint32_t ax = smem_u32_of(&sX[0][0][0]);
    const uint32_t ab = smem_u32_of(&sB[0][0][0]);
    const uint32_t ac = smem_u32_of(&sC[0][0][0]);

    ull st2[4];
#pragma unroll
    for (int i = 0; i < 4; i++) st2[i] = 0ull;

    const float Dh = Dp[h];
    const size_t rowbase = (size_t)b * SEQ;
    const int boff = DI + half * 32;
    const int coff = DI + NSTATE + half * 32;
    float* yout = half ? g_y2 : g_y;

    // per-chunk cooperative async load: sX 256 tasks, sB/sC 128 each; dt/dA regular
#define SLOAD(c) do {                                                        \
    const int s_ = (c) & 1;                                                  \
    const size_t r0_ = rowbase + (size_t)(c) * 16;                           \
    { const int t_ = tid >> 4, sg_ = tid & 15;                               \
      cp16(ax + s_ * 4096 + t_ * 256 + sg_ * 16,                             \
           g_conv + (r0_ + t_) * (size_t)CDIM + h * 64 + sg_ * 4); }         \
    if (tid < 128) {                                                         \
      const int t_ = tid >> 3, sg_ = tid & 7;                                \
      cp16(ab + s_ * 2048 + t_ * 128 + sg_ * 16,                             \
           g_conv + (r0_ + t_) * (size_t)CDIM + boff + sg_ * 4);             \
    } else {                                                                 \
      const int u_ = tid - 128;                                              \
      const int t_ = u_ >> 3, sg_ = u_ & 7;                                  \
      cp16(ac + s_ * 2048 + t_ * 128 + sg_ * 16,                             \
           g_conv + (r0_ + t_) * (size_t)CDIM + coff + sg_ * 4);             \
    }                                                                        \
    if (tid < 16)       sdt[s_][tid]      = g_dt[(r0_ + tid) * NH + h];      \
    else if (tid < 32)  sda[s_][tid - 16] = g_dA[(r0_ + tid - 16) * NH + h]; \
    cp_commit();                                                             \
} while (0)

    SLOAD(0);

    for (int c = 0; c < SEQ / 16; c++) {
        const int buf = c & 1;
        if (c + 1 < SEQ / 16) { SLOAD(c + 1); cp_wait<1>(); }
        else cp_wait<0>();
        __syncthreads();

        ull acc2[16];
#pragma unroll
        for (int t = 0; t < 16; t++) acc2[t] = 0ull;

#pragma unroll
        for (int t = 0; t < 16; t++) {
            const float dtx = sdt[buf][t] * sX[buf][t][p];
            const ull dtx2 = dup2(dtx);
            const ull dav2 = dup2(sda[buf][t]);
            const ulonglong2 b01 = *(const ulonglong2*)&sB[buf][t][nb];
            const ulonglong2 b23 = *(const ulonglong2*)&sB[buf][t][nb + 4];
            const ulonglong2 c01 = *(const ulonglong2*)&sC[buf][t][nb];
            const ulonglong2 c23 = *(const ulonglong2*)&sC[buf][t][nb + 4];
            const ull m0 = ffma2(dtx2, b01.x, 0ull);
            const ull m1 = ffma2(dtx2, b01.y, 0ull);
            const ull m2 = ffma2(dtx2, b23.x, 0ull);
            const ull m3 = ffma2(dtx2, b23.y, 0ull);
            st2[0] = ffma2(dav2, st2[0], m0);
            st2[1] = ffma2(dav2, st2[1], m1);
            st2[2] = ffma2(dav2, st2[2], m2);
            st2[3] = ffma2(dav2, st2[3], m3);
            ull a = acc2[t];
            a = ffma2(st2[0], c01.x, a);
            a = ffma2(st2[1], c01.y, a);
            a = ffma2(st2[2], c23.x, a);
            a = ffma2(st2[3], c23.y, a);
            acc2[t] = a;
        }

        // deferred reduction: horizontal + 2 pipelined shfl rounds
        float accs[16];
#pragma unroll
        for (int t = 0; t < 16; t++) accs[t] = hsum2(acc2[t]);
#pragma unroll
        for (int t = 0; t < 16; t++) accs[t] += __shfl_xor_sync(0xffffffffu, accs[t], 1);
#pragma unroll
        for (int t = 0; t < 16; t++) accs[t] += __shfl_xor_sync(0xffffffffu, accs[t], 2);
        if (g == 0) {
#pragma unroll
            for (int t = 0; t < 16; t++) sY[t][p] = accs[t];
        }
        __syncthreads();

        // coalesced output write (+ D*x skip on half 0)
#pragma unroll
        for (int i = tid; i < 16 * 64; i += 256) {
            const int t = i >> 6, j = i & 63;
            const float skip = half ? 0.f : Dh * sX[buf][t][j];
            yout[(rowbase + c * 16 + t) * (size_t)DI + h * 64 + j] = sY[t][j] + skip;
        }
        __syncthreads();   // protect sX[buf]/sY before next SLOAD overwrites
    }
#undef SLOAD
}

// ---------------- gate (silu(z)) + RMSNorm -> fp16 hi/lo ----------------
__global__ void gaterms_kernel(const float* __restrict__ rw)
{
    __shared__ float sh[8];
    const int row = blockIdx.x;
    const int tid = threadIdx.x;
    const float* yr = g_y  + (size_t)row * DI;
    const float* y2 = g_y2 + (size_t)row * DI;
    const float* zr = g_zx + (size_t)row * DIP;
    float vals[8];
    float s2 = 0.f;
#pragma unroll
    for (int u = 0; u < 2; u++) {
        const int j = tid * 4 + u * 1024;
        const float4 yv = *(const float4*)(yr + j);
        const float4 y2v = *(const float4*)(y2 + j);
        const float4 zv = *(const float4*)(zr + j);
        const float y0 = yv.x + y2v.x, y1 = yv.y + y2v.y;
        const float y2s = yv.z + y2v.z, y3 = yv.w + y2v.w;
        const float g0 = y0 * (zv.x / (1.f + expf(-zv.x)));
        const float g1 = y1 * (zv.y / (1.f + expf(-zv.y)));
        const float g2 = y2s * (zv.z / (1.f + expf(-zv.z)));
        const float g3 = y3 * (zv.w / (1.f + expf(-zv.w)));
        vals[u*4+0] = g0; vals[u*4+1] = g1; vals[u*4+2] = g2; vals[u*4+3] = g3;
        s2 += g0*g0 + g1*g1 + g2*g2 + g3*g3;
    }
#pragma unroll
    for (int o = 16; o; o >>= 1) s2 += __shfl_xor_sync(0xffffffffu, s2, o);
    if ((tid & 31) == 0) sh[tid >> 5] = s2;
    __syncthreads();
    if (tid < 32) {
        s2 = (tid < 8) ? sh[tid] : 0.f;
#pragma unroll
        for (int o = 4; o; o >>= 1) s2 += __shfl_xor_sync(0xffffffffu, s2, o);
        if (tid == 0) sh[0] = s2;
    }
    __syncthreads();
    const float scale = rsqrtf(sh[0] * (1.f / DI) + 1e-5f);
#pragma unroll
    for (int u = 0; u < 2; u++) {
        const int j = tid * 4 + u * 1024;
        const float4 wv = *(const float4*)(rw + j);
        const float o0 = vals[u*4+0] * scale * wv.x;
        const float o1 = vals[u*4+1] * scale * wv.y;
        const float o2 = vals[u*4+2] * scale * wv.z;
        const float o3 = vals[u*4+3] * scale * wv.w;
        __half h0,h1,h2,h3,l0,l1,l2,l3;
        split_h(o0,h0,l0); split_h(o1,h1,l1); split_h(o2,h2,l2); split_h(o3,h3,l3);
        __half2 p;
        __half2* hp = (__half2*)(g_yh + (size_t)row * DI + j);
        __half2* lp = (__half2*)(g_yl + (size_t)row * DI + j);
        p.x=h0; p.y=h1; hp[0]=p;  p.x=h2; p.y=h3; hp[1]=p;
        p.x=l0; p.y=l1; lp[0]=p;  p.x=l2; p.y=l3; lp[1]=p;
    }
}

// ---------------- host launch ----------------
extern "C" void kernel_launch(void* const* d_in, const int* in_sizes, int n_in,
                              void* d_out, int out_size)
{
    const float* x       = (const float*)d_in[0];
    const float* ln_w    = (const float*)d_in[1];
    const float* ln_b    = (const float*)d_in[2];
    const float* in_proj = (const float*)d_in[3];
    const float* conv_w  = (const float*)d_in[4];
    const float* conv_b  = (const float*)d_in[5];
    const float* dt_bias = (const float*)d_in[6];
    const float* A_log   = (const float*)d_in[7];
    const float* Dvec    = (const float*)d_in[8];
    const float* rms_w   = (const float*)d_in[9];
    const float* out_w   = (const float*)d_in[10];
    float* out = (float*)d_out;

    float *p_h, *p_zx;
    __half *p_xh, *p_xl, *p_yh, *p_yl, *p_wh;
    cudaGetSymbolAddress((void**)&p_h,  g_h);
    cudaGetSymbolAddress((void**)&p_zx, g_zx);
    cudaGetSymbolAddress((void**)&p_xh, g_xh);
    cudaGetSymbolAddress((void**)&p_xl, g_xl);
    cudaGetSymbolAddress((void**)&p_yh, g_yh);
    cudaGetSymbolAddress((void**)&p_yl, g_yl);
    cudaGetSymbolAddress((void**)&p_wh, g_wh);

    cudaFuncSetAttribute(gemm_mma, cudaFuncAttributeMaxDynamicSharedMemorySize, GEMM_SMEM);

    for (int i = 0; i < 2; i++) {
        const float* hin  = (i == 0) ? x   : p_h;
        float*       hout = (i == 0) ? p_h : out;

        ln_kernel<<<M_ROWS, 256>>>(hin, ln_w + i * DM, ln_b + i * DM, p_xh, p_xl);

        cvt_f16<<<(DIP * DM / 4) / 256, 256>>>(in_proj + (size_t)i * DIP * DM, p_wh);

        gemm_mma<<<dim3((DIP + 127) / 128, M_ROWS / 256), 256, GEMM_SMEM>>>(
            p_xh, p_xl, p_wh, nullptr, p_zx, DIP, DM);

        dt_kernel<<<(M_ROWS * NH) / 256, 256>>>(dt_bias + i * NH, A_log + i * NH);

        conv_kernel<<<(M_ROWS * CDIM + 255) / 256, 256>>>(
            conv_w + (size_t)i * CDIM * 4, conv_b + (size_t)i * CDIM);

        scan_kernel<<<2 * BATCH * NH, 256>>>(Dvec + i * NH);

        gaterms_kernel<<<M_ROWS, 256>>>(rms_w + (size_t)i * DI);

        cvt_f16<<<(DM * DI / 4) / 256, 256>>>(out_w + (size_t)i * DM * DI, p_wh);

        gemm_mma<<<dim3(DM / 128, M_ROWS / 256), 256, GEMM_SMEM>>>(
            p_yh, p_yl, p_wh, hin, hout, DM, DI);
    }
}